// round 17
// baseline (speedup 1.0000x reference)
#include <cuda_runtime.h>
#include <cuda_bf16.h>
#include <cstdint>

// ---------------- problem constants ----------------
#define BB    8
#define CN    128
#define HN    128
#define WN    128
#define HWN   16384
#define CHWN  (CN*HWN)                 // 2,097,152
#define BCHWN (BB*CHWN)                // 16,777,216
#define NPIX  (BB*HWN)                 // 131,072
#define NSPLIT 32

// bf16 pair layout: [k2][m] of uint2 {hi_bf16x2, lo_bf16x2}, pitch 131
#define PB 131
#define BF_TILE (32*PB*8)              // 33536
#define SMEM_BF (2*BF_TILE + 512)
// ln smem: B2a | B2b | A2 | stats
#define SMEM_LN3 (3*BF_TILE + 4096)

// ---------------- device scratch ----------------
__device__ float g_pre [6ull*BCHWN];                        // conv1x1 out (fp32)
__device__ __align__(16) uint32_t g_postall[6ull*BCHWN];    // dw out, bf16 packed
__device__ float g_Spart[2ull*NSPLIT*BB*CN*CN];
__device__ __align__(16) uint32_t g_S2[2ull*BB*CN*CN];      // softmax (bf16 packed)
__device__ __align__(16) uint32_t g_A [2ull*BCHWN];         // attn out (bf16 packed)
__device__ float g_lin [1ull*BCHWN];
__device__ __align__(16) uint32_t g_w2b [6*CN*CN];          // 1x1 W (bf16 packed)
__device__ __align__(16) uint32_t g_lw2b[2*CN*CN];          // lw (bf16 packed)

// ---------------- splits ----------------
__device__ __forceinline__ uint32_t bsplit(float x) {       // bf16 hi/lo packed
    __nv_bfloat16 h = __float2bfloat16(x);
    float l = x - __bfloat162float(h);
    __nv_bfloat16 lo = __float2bfloat16(l);
    return ((uint32_t)__bfloat16_as_ushort(lo) << 16) |
           (uint32_t)__bfloat16_as_ushort(h);
}
__device__ __forceinline__ uint2 bpack2(float v0, float v1) {
    __nv_bfloat16 h0 = __float2bfloat16(v0);
    __nv_bfloat16 h1 = __float2bfloat16(v1);
    __nv_bfloat16 l0 = __float2bfloat16(v0 - __bfloat162float(h0));
    __nv_bfloat16 l1 = __float2bfloat16(v1 - __bfloat162float(h1));
    uint2 r;
    r.x = ((uint32_t)__bfloat16_as_ushort(h1) << 16) | (uint32_t)__bfloat16_as_ushort(h0);
    r.y = ((uint32_t)__bfloat16_as_ushort(l1) << 16) | (uint32_t)__bfloat16_as_ushort(l0);
    return r;
}

// ---------------- mma wrapper ----------------
__device__ __forceinline__ void mmabf(float c[4], const uint32_t a[4],
                                      uint32_t b0, uint32_t b1) {
    asm volatile(
        "mma.sync.aligned.m16n8k16.row.col.f32.bf16.bf16.f32 "
        "{%0,%1,%2,%3},{%4,%5,%6,%7},{%8,%9},{%0,%1,%2,%3};"
        : "+f"(c[0]), "+f"(c[1]), "+f"(c[2]), "+f"(c[3])
        : "r"(a[0]), "r"(a[1]), "r"(a[2]), "r"(a[3]), "r"(b0), "r"(b1));
}
#define ZERO_C48(c4) {                                 \
    _Pragma("unroll") for (int mi = 0; mi < 2; mi++)   \
    _Pragma("unroll") for (int ni = 0; ni < 8; ni++)   \
    _Pragma("unroll") for (int t = 0; t < 4; t++) (c4)[mi][ni][t] = 0.f; }

// bf16 pair KM/KM, K=64 chunk (32 k2-rows), warp tile 32x64
__device__ __forceinline__ void gemm_bf(const uint2* __restrict__ A2,
                                        const uint2* __restrict__ B2,
                                        float c4[2][8][4],
                                        int m0, int n0w, int r, int q) {
#pragma unroll
    for (int ks = 0; ks < 4; ks++) {
        int k2a = ks * 8 + q, k2b = ks * 8 + q + 4;
        uint32_t ah[2][4], al[2][4];
#pragma unroll
        for (int mi = 0; mi < 2; mi++) {
            int m = m0 + mi * 16 + r;
            uint2 u0 = A2[k2a * PB + m];
            uint2 u1 = A2[k2a * PB + m + 8];
            uint2 u2 = A2[k2b * PB + m];
            uint2 u3 = A2[k2b * PB + m + 8];
            ah[mi][0] = u0.x; ah[mi][1] = u1.x; ah[mi][2] = u2.x; ah[mi][3] = u3.x;
            al[mi][0] = u0.y; al[mi][1] = u1.y; al[mi][2] = u2.y; al[mi][3] = u3.y;
        }
#pragma unroll
        for (int ni = 0; ni < 8; ni++) {
            int col = n0w + ni * 8 + r;
            uint2 v0 = B2[k2a * PB + col];
            uint2 v1 = B2[k2b * PB + col];
#pragma unroll
            for (int mi = 0; mi < 2; mi++) {
                mmabf(c4[mi][ni], ah[mi], v0.x, v1.x);
                mmabf(c4[mi][ni], al[mi], v0.x, v1.x);
                mmabf(c4[mi][ni], ah[mi], v0.y, v1.y);
            }
        }
    }
}

// ---------------- kernel 0b: pre-split weights (all bf16 packed) -----------
__global__ __launch_bounds__(256) void k_splitw(
    const float* w0, const float* w1, const float* w2,
    const float* w3, const float* w4, const float* w5,
    const float* lw) {
    int i = blockIdx.x * 256 + threadIdx.x;
    if (i < 6 * CN * CN) {
        const float* srcs[6] = {w0, w1, w2, w3, w4, w5};
        g_w2b[i] = bsplit(srcs[i >> 14][i & 16383]);
    } else {
        int j = i - 6 * CN * CN;
        g_lw2b[j] = bsplit(lw[j]);
    }
}

// ---------------- kernel 1: fused stats + LN + 3x(1x1 conv) (bf16x3) ------
// C[o][pix] = sum_c W[o][c] * Xn[pix][c]; A=W [c2][o], B=Xn [c2][pix]
__global__ __launch_bounds__(256, 2) void k_ln_c11(
    const float* __restrict__ Fi, const float* __restrict__ Fw,
    const float* __restrict__ g1, const float* __restrict__ g2,
    const float* bq, const float* bk, const float* bv,
    const float* bq2, const float* bk2, const float* bv2) {
    extern __shared__ char smraw[];
    uint2* B2a = (uint2*)smraw;
    uint2* B2b = (uint2*)(smraw + BF_TILE);
    uint2* A2  = (uint2*)(smraw + 2 * BF_TILE);
    float* mu_s = (float*)(smraw + 3 * BF_TILE);
    float* rs_s = mu_s + 128;
    float* gm_s = rs_s + 128;
    float* redS = gm_s + 128;                          // [2][128]
    float* redQ = redS + 256;                          // [2][128]

    int tid = threadIdx.x, wid = tid >> 5, lane = tid & 31;
    int inp = blockIdx.y;
    int p0 = blockIdx.x * 128;
    int b = p0 >> 14, pix0 = p0 & (HWN - 1);
    const float* X = inp ? Fw : Fi;
    const float* gamma = inp ? g2 : g1;
    const float* Bs3[3] = { inp ? bq2 : bq, inp ? bk2 : bk, inp ? bv2 : bv };

    if (tid < 128) gm_s[tid] = gamma[tid];

    // phase A: LN stats straight from gmem (coalesced)
    const float* Xb = X + (size_t)b * CHWN + pix0;
    {
        int p = tid & 127, g = tid >> 7;
        float s = 0.f, ss = 0.f;
#pragma unroll 8
        for (int kc = g * 64; kc < g * 64 + 64; kc++) {
            float v = Xb[(size_t)kc * HWN + p];
            s += v; ss += v * v;
        }
        redS[g * 128 + p] = s;
        redQ[g * 128 + p] = ss;
    }
    __syncthreads();
    if (tid < 128) {
        float s  = redS[tid] + redS[128 + tid];
        float ss = redQ[tid] + redQ[128 + tid];
        float m = s * (1.f / CN);
        mu_s[tid] = m;
        rs_s[tid] = rsqrtf(ss * (1.f / CN) - m * m + 1e-5f);
    }
    __syncthreads();

    // phase B: re-read X (L2 hot), normalize + pack into B tiles [c2][pix]
#pragma unroll 8
    for (int it = 0; it < 32; it++) {
        int idx = it * 256 + tid;                      // 8192 = 64 c2 x 128 p
        int c2 = idx >> 7, p = idx & 127;
        float mu = mu_s[p], rs = rs_s[p];
        float v0 = (Xb[(size_t)(2 * c2) * HWN + p] - mu) * rs * gm_s[2 * c2];
        float v1 = (Xb[(size_t)(2 * c2 + 1) * HWN + p] - mu) * rs * gm_s[2 * c2 + 1];
        uint2 pk = bpack2(v0, v1);
        if (c2 < 32) B2a[c2 * PB + p] = pk;
        else         B2b[(c2 - 32) * PB + p] = pk;
    }

    int m0 = (wid & 3) * 32, n0w = (wid >> 2) * 64;
    int r = lane >> 2, q = lane & 3;

    for (int i = 0; i < 3; i++) {
        const uint32_t* Wsrc = g_w2b + (size_t)(inp * 3 + i) * CN * CN;
        float c4[2][8][4];
        ZERO_C48(c4);
#pragma unroll 2
        for (int ch = 0; ch < 2; ch++) {
            __syncthreads();
#pragma unroll
            for (int it = 0; it < 8; it++) {           // A = W [c2][o]
                int idx = it * 256 + tid;
                int cg = idx & 15, o = idx >> 4;
                uint4 wv = *(const uint4*)(Wsrc + o * CN + ch * 64 + 4 * cg);
                A2[(2 * cg) * PB + o] =
                    make_uint2(__byte_perm(wv.x, wv.y, 0x5410), __byte_perm(wv.x, wv.y, 0x7632));
                A2[(2 * cg + 1) * PB + o] =
                    make_uint2(__byte_perm(wv.z, wv.w, 0x5410), __byte_perm(wv.z, wv.w, 0x7632));
            }
            __syncthreads();
            gemm_bf(A2, ch ? B2b : B2a, c4, m0, n0w, r, q);
        }
        const float* bias = Bs3[i];
        float* Ob = g_pre + ((size_t)(inp * 3 + i) * BB + b) * CHWN;
#pragma unroll
        for (int mi = 0; mi < 2; mi++) {
            int o0 = m0 + mi * 16 + r;
            float bo0 = __ldg(&bias[o0]), bo1 = __ldg(&bias[o0 + 8]);
#pragma unroll
            for (int ni = 0; ni < 8; ni++) {
                int col = pix0 + n0w + ni * 8 + 2 * q;
                *(float2*)&Ob[(size_t)o0 * HWN + col] =
                    make_float2(c4[mi][ni][0] + bo0, c4[mi][ni][1] + bo0);
                *(float2*)&Ob[(size_t)(o0 + 8) * HWN + col] =
                    make_float2(c4[mi][ni][2] + bo1, c4[mi][ni][3] + bo1);
            }
        }
    }
}

// ---------------- kernel 2: depthwise 3x3, smem-tiled, bf16 out ------------
__global__ __launch_bounds__(256) void k_dw(
    const float* d0, const float* d1, const float* d2,
    const float* d3, const float* d4, const float* d5,
    const float* e0, const float* e1, const float* e2,
    const float* e3, const float* e4, const float* e5) {
    __shared__ float s[10][128];
    int br = blockIdx.z, b = blockIdx.y;
    int c = blockIdx.x >> 4, rg = blockIdx.x & 15;
    int h0 = rg * 8;
    int tid = threadIdx.x;
    const float* Wd6[6] = {d0, d1, d2, d3, d4, d5};
    const float* Bd6[6] = {e0, e1, e2, e3, e4, e5};
    const float* In = g_pre + ((size_t)br * BB + b) * CHWN + (size_t)c * HWN;

#pragma unroll
    for (int i = tid; i < 1280; i += 256) {
        int row = i >> 7, col = i & 127;
        int gh = h0 - 1 + row;
        s[row][col] = ((unsigned)gh < 128u) ? In[(size_t)gh * WN + col] : 0.f;
    }
    __syncthreads();

    const float* Wd = Wd6[br] + c * 9;
    float kw[9];
#pragma unroll
    for (int i = 0; i < 9; i++) kw[i] = __ldg(&Wd[i]);
    float bias = __ldg(&Bd6[br][c]);

    int t4 = tid * 4, lr = t4 >> 7, w0 = t4 & 127;
    float a0 = bias, a1 = bias, a2 = bias, a3 = bias;
#pragma unroll
    for (int dy = 0; dy < 3; dy++) {
        const float* row = s[lr + dy];
        float4 v = *(const float4*)(row + w0);
        float xl = (w0 > 0)   ? row[w0 - 1] : 0.f;
        float xr = (w0 < 124) ? row[w0 + 4] : 0.f;
        float k0 = kw[dy * 3], k1 = kw[dy * 3 + 1], k2 = kw[dy * 3 + 2];
        a0 += k0 * xl  + k1 * v.x + k2 * v.y;
        a1 += k0 * v.x + k1 * v.y + k2 * v.z;
        a2 += k0 * v.y + k1 * v.z + k2 * v.w;
        a3 += k0 * v.z + k1 * v.w + k2 * xr;
    }
    uint32_t* Op = g_postall + ((size_t)br * BB + b) * CHWN + (size_t)c * HWN
                 + (size_t)h0 * WN + t4;
    *(uint4*)Op = make_uint4(bsplit(a0), bsplit(a1), bsplit(a2), bsplit(a3));
}

// ---------------- kernel 3: S partials (bf16x3) ----------------
// C[c][d] = sum_n Q[n][c] K[n][d]
__global__ __launch_bounds__(256, 3) void k_qk() {
    extern __shared__ char smraw[];
    uint2* A2 = (uint2*)smraw;
    uint2* B2 = (uint2*)(smraw + BF_TILE);
    int tid = threadIdx.x, wid = tid >> 5, lane = tid & 31;
    int s = blockIdx.x, b = blockIdx.y, att = blockIdx.z;
    int qbr = (att == 0) ? 0 : 3;
    int kbr = (att == 0) ? 4 : 1;
    const uint32_t* Qp = g_postall + ((size_t)qbr * BB + b) * CHWN;
    const uint32_t* Kp = g_postall + ((size_t)kbr * BB + b) * CHWN;

    int m0 = (wid & 3) * 32, n0w = (wid >> 2) * 64;
    int r = lane >> 2, q = lane & 3;
    float c4[2][8][4];
    ZERO_C48(c4);

    for (int ch = 0; ch < (HWN / NSPLIT / 64); ch++) {
        size_t nb = ((size_t)s * (HWN / NSPLIT) + ch * 64) * CN;
        __syncthreads();
#pragma unroll
        for (int it = 0; it < 4; it++) {
            int idx = it * 256 + tid;
            int n2 = idx >> 5, c4i = (idx & 31) * 4;
            uint4 q0 = *(const uint4*)(Qp + nb + (size_t)(2 * n2) * CN + c4i);
            uint4 q1 = *(const uint4*)(Qp + nb + (size_t)(2 * n2 + 1) * CN + c4i);
            uint2* da = A2 + n2 * PB + c4i;
            da[0] = make_uint2(__byte_perm(q0.x, q1.x, 0x5410), __byte_perm(q0.x, q1.x, 0x7632));
            da[1] = make_uint2(__byte_perm(q0.y, q1.y, 0x5410), __byte_perm(q0.y, q1.y, 0x7632));
            da[2] = make_uint2(__byte_perm(q0.z, q1.z, 0x5410), __byte_perm(q0.z, q1.z, 0x7632));
            da[3] = make_uint2(__byte_perm(q0.w, q1.w, 0x5410), __byte_perm(q0.w, q1.w, 0x7632));
            uint4 k0 = *(const uint4*)(Kp + nb + (size_t)(2 * n2) * CN + c4i);
            uint4 k1 = *(const uint4*)(Kp + nb + (size_t)(2 * n2 + 1) * CN + c4i);
            uint2* db = B2 + n2 * PB + c4i;
            db[0] = make_uint2(__byte_perm(k0.x, k1.x, 0x5410), __byte_perm(k0.x, k1.x, 0x7632));
            db[1] = make_uint2(__byte_perm(k0.y, k1.y, 0x5410), __byte_perm(k0.y, k1.y, 0x7632));
            db[2] = make_uint2(__byte_perm(k0.z, k1.z, 0x5410), __byte_perm(k0.z, k1.z, 0x7632));
            db[3] = make_uint2(__byte_perm(k0.w, k1.w, 0x5410), __byte_perm(k0.w, k1.w, 0x7632));
        }
        __syncthreads();
        gemm_bf(A2, B2, c4, m0, n0w, r, q);
    }

    float* Sp = g_Spart + ((size_t)(att * NSPLIT + s) * BB + b) * (CN * CN);
#pragma unroll
    for (int mi = 0; mi < 2; mi++) {
        int c0 = m0 + mi * 16 + r;
#pragma unroll
        for (int ni = 0; ni < 8; ni++) {
            int col = n0w + ni * 8 + 2 * q;
            *(float2*)&Sp[c0 * CN + col] = make_float2(c4[mi][ni][0], c4[mi][ni][1]);
            *(float2*)&Sp[(c0 + 8) * CN + col] = make_float2(c4[mi][ni][2], c4[mi][ni][3]);
        }
    }
}

// ---------------- kernel 4: reduce partials + softmax -> bf16 packed --------
__global__ __launch_bounds__(256) void k_softmax() {
    int row  = blockIdx.x * 8 + (threadIdx.x >> 5);
    int lane = threadIdx.x & 31;
    int att = row >> 10, rb = row & 1023, b = rb >> 7, c = rb & 127;
    float v[4];
#pragma unroll
    for (int q = 0; q < 4; q++) {
        int d = lane + 32 * q;
        float s = 0.f;
        for (int sp = 0; sp < NSPLIT; sp++)
            s += g_Spart[((size_t)(att * NSPLIT + sp) * BB + b) * (CN * CN) + c * CN + d];
        v[q] = s;
    }
    float mx = fmaxf(fmaxf(v[0], v[1]), fmaxf(v[2], v[3]));
#pragma unroll
    for (int o = 16; o > 0; o >>= 1) mx = fmaxf(mx, __shfl_xor_sync(0xffffffffu, mx, o));
    float e[4], sum = 0.f;
#pragma unroll
    for (int q = 0; q < 4; q++) { e[q] = __expf(v[q] - mx); sum += e[q]; }
#pragma unroll
    for (int o = 16; o > 0; o >>= 1) sum += __shfl_xor_sync(0xffffffffu, sum, o);
    float inv = 1.f / sum;
#pragma unroll
    for (int q = 0; q < 4; q++)
        g_S2[(size_t)(att * BB + b) * (CN * CN) + c * CN + lane + 32 * q] =
            bsplit(e[q] * inv);
}

// ---------------- kernel 5: A@V (bf16x3) ----------------
__global__ __launch_bounds__(256, 3) void k_av() {
    extern __shared__ char smraw[];
    uint2* A2 = (uint2*)smraw;
    uint2* B2 = (uint2*)(smraw + BF_TILE);
    int tid = threadIdx.x, wid = tid >> 5, lane = tid & 31;
    int nt = blockIdx.x, b = blockIdx.y, att = blockIdx.z;
    int vbr = (att == 0) ? 5 : 2;
    const uint32_t* Sp = g_S2 + (size_t)(att * BB + b) * (CN * CN);
    const uint32_t* Vp = g_postall + ((size_t)vbr * BB + b) * CHWN;
    int n0 = nt * 128;

    int m0 = (wid & 3) * 32, n0w = (wid >> 2) * 64;
    int r = lane >> 2, q = lane & 3;
    float c4[2][8][4];
    ZERO_C48(c4);

#pragma unroll 2
    for (int chk = 0; chk < 2; chk++) {
        int d0 = chk * 64;
        __syncthreads();
#pragma unroll
        for (int it = 0; it < 4; it++) {               // A = V [d2][p]
            int idx = it * 256 + tid;
            int d2 = idx >> 5, p4 = (idx & 31) * 4;
            uint4 v0 = *(const uint4*)(Vp + (size_t)(d0 + 2 * d2) * HWN + n0 + p4);
            uint4 v1 = *(const uint4*)(Vp + (size_t)(d0 + 2 * d2 + 1) * HWN + n0 + p4);
            uint2* dst = A2 + d2 * PB + p4;
            dst[0] = make_uint2(__byte_perm(v0.x, v1.x, 0x5410), __byte_perm(v0.x, v1.x, 0x7632));
            dst[1] = make_uint2(__byte_perm(v0.y, v1.y, 0x5410), __byte_perm(v0.y, v1.y, 0x7632));
            dst[2] = make_uint2(__byte_perm(v0.z, v1.z, 0x5410), __byte_perm(v0.z, v1.z, 0x7632));
            dst[3] = make_uint2(__byte_perm(v0.w, v1.w, 0x5410), __byte_perm(v0.w, v1.w, 0x7632));
        }
#pragma unroll
        for (int it = 0; it < 8; it++) {               // B = S [d2][c]
            int idx = it * 256 + tid;
            int d2g = idx & 15, c = idx >> 4;
            uint4 sv = *(const uint4*)(Sp + c * CN + d0 + 4 * d2g);
            B2[(2 * d2g) * PB + c] =
                make_uint2(__byte_perm(sv.x, sv.y, 0x5410), __byte_perm(sv.x, sv.y, 0x7632));
            B2[(2 * d2g + 1) * PB + c] =
                make_uint2(__byte_perm(sv.z, sv.w, 0x5410), __byte_perm(sv.z, sv.w, 0x7632));
        }
        __syncthreads();
        gemm_bf(A2, B2, c4, m0, n0w, r, q);
    }

    uint32_t* Out = g_A + (size_t)att * BCHWN + (size_t)b * CHWN;
#pragma unroll
    for (int mi = 0; mi < 2; mi++) {
        int rr = m0 + mi * 16 + r;
#pragma unroll
        for (int ni = 0; ni < 8; ni++) {
            int cc = n0w + ni * 8 + 2 * q;
            Out[(size_t)cc * HWN + n0 + rr]           = bsplit(c4[mi][ni][0]);
            Out[(size_t)(cc + 1) * HWN + n0 + rr]     = bsplit(c4[mi][ni][1]);
            Out[(size_t)cc * HWN + n0 + rr + 8]       = bsplit(c4[mi][ni][2]);
            Out[(size_t)(cc + 1) * HWN + n0 + rr + 8] = bsplit(c4[mi][ni][3]);
        }
    }
}

// ---------------- kernel 6: final linear (bf16x3) ----------------
__global__ __launch_bounds__(256, 3) void k_final(const float* __restrict__ lb) {
    extern __shared__ char smraw[];
    uint2* A2 = (uint2*)smraw;
    uint2* B2 = (uint2*)(smraw + BF_TILE);
    int tid = threadIdx.x, wid = tid >> 5, lane = tid & 31;
    int nt = blockIdx.x, b = blockIdx.y;
    int n0 = nt * 128;

    int m0 = (wid & 3) * 32, n0w = (wid >> 2) * 64;
    int r = lane >> 2, q = lane & 3;
    float c4[2][8][4];
    ZERO_C48(c4);

    for (int chk = 0; chk < 4; chk++) {
        int part = chk >> 1, tloc = (chk & 1) * 64;
        const uint32_t* Ap = g_A + ((size_t)part * BB + b) * CHWN + (size_t)n0 * CN;
        __syncthreads();
#pragma unroll
        for (int it = 0; it < 8; it++) {               // A = flat [t2][pix]
            int idx = it * 256 + tid;
            int tg = idx & 15, p = idx >> 4;
            uint4 av = *(const uint4*)(Ap + p * CN + tloc + 4 * tg);
            A2[(2 * tg) * PB + p] =
                make_uint2(__byte_perm(av.x, av.y, 0x5410), __byte_perm(av.x, av.y, 0x7632));
            A2[(2 * tg + 1) * PB + p] =
                make_uint2(__byte_perm(av.z, av.w, 0x5410), __byte_perm(av.z, av.w, 0x7632));
        }
#pragma unroll
        for (int it = 0; it < 8; it++) {               // B = lw [t2][co]
            int idx = it * 256 + tid;
            int tg = idx & 15, co = idx >> 4;
            uint4 lv = *(const uint4*)(g_lw2b + co * 256 + part * 128 + tloc + 4 * tg);
            B2[(2 * tg) * PB + co] =
                make_uint2(__byte_perm(lv.x, lv.y, 0x5410), __byte_perm(lv.x, lv.y, 0x7632));
            B2[(2 * tg + 1) * PB + co] =
                make_uint2(__byte_perm(lv.z, lv.w, 0x5410), __byte_perm(lv.z, lv.w, 0x7632));
        }
        __syncthreads();
        gemm_bf(A2, B2, c4, m0, n0w, r, q);
    }

    float* Ob = g_lin + (size_t)b * CHWN;
#pragma unroll
    for (int mi = 0; mi < 2; mi++) {
        int p0r = n0 + m0 + mi * 16 + r;
#pragma unroll
        for (int ni = 0; ni < 8; ni++) {
            int col = n0w + ni * 8 + 2 * q;
            float b0 = __ldg(&lb[col]), b1 = __ldg(&lb[col + 1]);
            *(float2*)&Ob[(size_t)p0r * CN + col] =
                make_float2(c4[mi][ni][0] + b0, c4[mi][ni][1] + b1);
            *(float2*)&Ob[(size_t)(p0r + 8) * CN + col] =
                make_float2(c4[mi][ni][2] + b0, c4[mi][ni][3] + b1);
        }
    }
}

// ---------------- kernel 7: tail transpose + residual ----------------
__global__ __launch_bounds__(256) void k_tail(const float* __restrict__ Fi,
                                              const float* __restrict__ Fw,
                                              float* __restrict__ out) {
    __shared__ float tile[32][33];
    int b  = blockIdx.z;
    int r0 = blockIdx.x * 32;
    int c0 = blockIdx.y * 32;
    const float* In = g_lin + (size_t)b * CHWN;
    int tx = threadIdx.x & 31, ty = threadIdx.x >> 5;
#pragma unroll
    for (int s2 = 0; s2 < 4; s2++) {
        int cc = c0 + ty + 8 * s2;
        tile[ty + 8 * s2][tx] = In[(size_t)cc * HWN + r0 + tx];
    }
    __syncthreads();
    size_t base = (size_t)b * CHWN;
#pragma unroll
    for (int s2 = 0; s2 < 4; s2++) {
        int r = r0 + ty + 8 * s2;
        size_t idx = base + (size_t)r * CN + c0 + tx;
        out[idx] = tile[tx][ty + 8 * s2] + Fi[idx] + Fw[idx];
    }
}

// ---------------- launch ----------------
extern "C" void kernel_launch(void* const* d_in, const int* in_sizes, int n_in,
                              void* d_out, int out_size) {
    const float* Fi = (const float*)d_in[0];
    const float* Fw = (const float*)d_in[1];
    const float* g1 = (const float*)d_in[2];
    const float* g2 = (const float*)d_in[3];

    const float *qw1, *kw1, *vw1, *qw2, *kw2, *vw2;
    const float *qb1, *kb1, *vb1, *qb2, *kb2, *vb2;
    const float *qdw1, *kdw1, *vdw1, *qdw2, *kdw2, *vdw2;
    const float *qdb1, *kdb1, *vdb1, *qdb2, *kdb2, *vdb2;
    const float *lw, *lb;

    if (in_sizes[5] == CN) {
        qw1 = (const float*)d_in[4];  qb1 = (const float*)d_in[5];
        kw1 = (const float*)d_in[6];  kb1 = (const float*)d_in[7];
        vw1 = (const float*)d_in[8];  vb1 = (const float*)d_in[9];
        qw2 = (const float*)d_in[10]; qb2 = (const float*)d_in[11];
        kw2 = (const float*)d_in[12]; kb2 = (const float*)d_in[13];
        vw2 = (const float*)d_in[14]; vb2 = (const float*)d_in[15];
        qdw1 = (const float*)d_in[16]; qdb1 = (const float*)d_in[17];
        kdw1 = (const float*)d_in[18]; kdb1 = (const float*)d_in[19];
        vdw1 = (const float*)d_in[20]; vdb1 = (const float*)d_in[21];
        qdw2 = (const float*)d_in[22]; qdb2 = (const float*)d_in[23];
        kdw2 = (const float*)d_in[24]; kdb2 = (const float*)d_in[25];
        vdw2 = (const float*)d_in[26]; vdb2 = (const float*)d_in[27];
    } else {
        qw1 = (const float*)d_in[4];  kw1 = (const float*)d_in[5];
        vw1 = (const float*)d_in[6];  qw2 = (const float*)d_in[7];
        kw2 = (const float*)d_in[8];  vw2 = (const float*)d_in[9];
        qb1 = (const float*)d_in[10]; kb1 = (const float*)d_in[11];
        vb1 = (const float*)d_in[12]; qb2 = (const float*)d_in[13];
        kb2 = (const float*)d_in[14]; vb2 = (const float*)d_in[15];
        qdw1 = (const float*)d_in[16]; kdw1 = (const float*)d_in[17];
        vdw1 = (const float*)d_in[18]; qdw2 = (const float*)d_in[19];
        kdw2 = (const float*)d_in[20]; vdw2 = (const float*)d_in[21];
        qdb1 = (const float*)d_in[22]; kdb1 = (const float*)d_in[23];
        vdb1 = (const float*)d_in[24]; qdb2 = (const float*)d_in[25];
        kdb2 = (const float*)d_in[26]; vdb2 = (const float*)d_in[27];
    }
    lw = (const float*)d_in[28];
    lb = (const float*)d_in[29];
    float* out = (float*)d_out;

    cudaFuncSetAttribute(k_ln_c11, cudaFuncAttributeMaxDynamicSharedMemorySize, SMEM_LN3);
    cudaFuncSetAttribute(k_qk,     cudaFuncAttributeMaxDynamicSharedMemorySize, SMEM_BF);
    cudaFuncSetAttribute(k_av,     cudaFuncAttributeMaxDynamicSharedMemorySize, SMEM_BF);
    cudaFuncSetAttribute(k_final,  cudaFuncAttributeMaxDynamicSharedMemorySize, SMEM_BF);

    k_splitw <<<dim3(512), 256>>>(qw1, kw1, vw1, qw2, kw2, vw2, lw);
    k_ln_c11 <<<dim3(NPIX / 128, 2), 256, SMEM_LN3>>>(Fi, Fw, g1, g2,
                                                      qb1, kb1, vb1, qb2, kb2, vb2);
    k_dw     <<<dim3(2048, BB, 6), 256>>>(qdw1, kdw1, vdw1, qdw2, kdw2, vdw2,
                                          qdb1, kdb1, vdb1, qdb2, kdb2, vdb2);
    k_qk     <<<dim3(NSPLIT, BB, 2), 256, SMEM_BF>>>();
    k_softmax<<<dim3(256), 256>>>();
    k_av     <<<dim3(HWN / 128, BB, 2), 256, SMEM_BF>>>();
    k_final  <<<dim3(HWN / 128, BB), 256, SMEM_BF>>>(lb);
    k_tail   <<<dim3(HWN / 32, CN / 32, BB), 256>>>(Fi, Fw, out);
}